// round 2
// baseline (speedup 1.0000x reference)
#include <cuda_runtime.h>
#include <cuda_bf16.h>

#define N_NODES 50000
#define KNB 16
#define DIM 256
#define LN_EPS 1e-5f

// Scratch for the weighted-gather output agg_in[N, DIM] (51.2 MB).
__device__ __align__(16) float g_agg[(size_t)N_NODES * DIM];
__device__ int g_is64;

// ---------------------------------------------------------------------------
// Detect whether the neighbors buffer is int64 or int32.
// If genuine int64: every 8-byte word is a valid index < N_NODES.
// If int32: an 8-byte word is (idx_lo | idx_hi<<32); idx_hi != 0 w.p. ~1-2e-5,
// so 64 consecutive all-< N words is astronomically unlikely.
// ---------------------------------------------------------------------------
__global__ void detect_idx_kernel(const void* __restrict__ nbr) {
    if (threadIdx.x == 0) {
        const unsigned long long* p = (const unsigned long long*)nbr;
        int ok = 1;
        #pragma unroll 1
        for (int i = 0; i < 64; i++) {
            if (p[i] >= (unsigned long long)N_NODES) { ok = 0; break; }
        }
        g_is64 = ok;
    }
}

// ---------------------------------------------------------------------------
// Weighted gather: one warp per node.
//   agg[n, :] = sum_k norm_w[n,k] * features[neighbors[n,k], :]
// Each lane owns 8 floats (2 float4) of the 256-dim row.
// ---------------------------------------------------------------------------
__global__ __launch_bounds__(256) void gather_kernel(
    const float4* __restrict__ feats,        // [N, DIM/4]
    const void*   __restrict__ nbr,          // [N, K] int32 or int64
    const float*  __restrict__ iw)           // [N, K]
{
    const unsigned FULL = 0xFFFFFFFFu;
    int warp = (blockIdx.x * blockDim.x + threadIdx.x) >> 5;
    int lane = threadIdx.x & 31;
    if (warp >= N_NODES) return;

    const int is64 = g_is64;

    float w = 0.0f;
    int   idx = 0;
    if (lane < KNB) {
        w = iw[(size_t)warp * KNB + lane];
        if (is64) idx = (int)(((const long long*)nbr)[(size_t)warp * KNB + lane]);
        else      idx = ((const int*)nbr)[(size_t)warp * KNB + lane];
    }
    // sum of the 16 weights (lanes 16..31 contribute 0)
    float ws = w;
    ws += __shfl_xor_sync(FULL, ws, 1);
    ws += __shfl_xor_sync(FULL, ws, 2);
    ws += __shfl_xor_sync(FULL, ws, 4);
    ws += __shfl_xor_sync(FULL, ws, 8);
    ws  = __shfl_sync(FULL, ws, 0);
    float nw = (ws == 0.0f) ? (1.0f / (float)KNB) : (w / ws);

    float4 acc0 = make_float4(0.f, 0.f, 0.f, 0.f);
    float4 acc1 = make_float4(0.f, 0.f, 0.f, 0.f);

    #pragma unroll
    for (int k = 0; k < KNB; k++) {
        int   ik = __shfl_sync(FULL, idx, k);
        float wk = __shfl_sync(FULL, nw,  k);
        const float4* row = feats + (size_t)ik * (DIM / 4);
        float4 f0 = row[lane];
        float4 f1 = row[lane + 32];
        acc0.x += wk * f0.x; acc0.y += wk * f0.y;
        acc0.z += wk * f0.z; acc0.w += wk * f0.w;
        acc1.x += wk * f1.x; acc1.y += wk * f1.y;
        acc1.z += wk * f1.z; acc1.w += wk * f1.w;
    }

    float4* out = (float4*)g_agg + (size_t)warp * (DIM / 4);
    out[lane]      = acc0;
    out[lane + 32] = acc1;
}

// ---------------------------------------------------------------------------
// Fused GEMM + bias + LayerNorm.
//   out = LN(agg @ W + b) * gamma + beta
// Block: 256 threads, tile M=32 rows x N=256 cols (full row -> LN in-block).
// Thread (ty = tid/32, tx = tid%32) owns rows ty*4..ty*4+3, cols tx + 32*j.
// Each warp owns 4 COMPLETE rows -> LayerNorm is a pure warp shuffle reduce.
// ---------------------------------------------------------------------------
#define MT 32
#define KB 32

__global__ __launch_bounds__(256) void gemm_ln_kernel(
    const float* __restrict__ W,      // [DIM, DIM]
    const float* __restrict__ bias,   // [DIM]
    const float* __restrict__ gamma,  // [DIM]
    const float* __restrict__ beta,   // [DIM]
    float* __restrict__ out)          // [N, DIM]
{
    __shared__ float As[MT * (KB + 1)];     // [row][kk], padded
    __shared__ float Ws[KB * DIM];          // [kk][col]

    const unsigned FULL = 0xFFFFFFFFu;
    int tid = threadIdx.x;
    int tx = tid & 31;
    int ty = tid >> 5;
    int row0 = blockIdx.x * MT;

    float acc[4][8];
    #pragma unroll
    for (int i = 0; i < 4; i++)
        #pragma unroll
        for (int j = 0; j < 8; j++) acc[i][j] = 0.0f;

    for (int k0 = 0; k0 < DIM; k0 += KB) {
        // Load A tile: 32 rows x 32 k (1024 elems, 4 per thread), coalesced.
        #pragma unroll
        for (int i = 0; i < 4; i++) {
            int li = tid + i * 256;
            int r  = li >> 5;
            int kk = li & 31;
            int grow = row0 + r;
            As[r * (KB + 1) + kk] =
                (grow < N_NODES) ? g_agg[(size_t)grow * DIM + k0 + kk] : 0.0f;
        }
        // Load W tile: 32 k x 256 cols (8192 elems, 32 per thread), coalesced.
        #pragma unroll
        for (int i = 0; i < KB; i++) {
            Ws[i * DIM + tid] = W[(size_t)(k0 + i) * DIM + tid];
        }
        __syncthreads();

        const float* Asr = &As[(ty * 4) * (KB + 1)];
        #pragma unroll 8
        for (int kk = 0; kk < KB; kk++) {
            float a0 = Asr[0 * (KB + 1) + kk];
            float a1 = Asr[1 * (KB + 1) + kk];
            float a2 = Asr[2 * (KB + 1) + kk];
            float a3 = Asr[3 * (KB + 1) + kk];
            const float* Wsk = &Ws[kk * DIM + tx];
            #pragma unroll
            for (int j = 0; j < 8; j++) {
                float wv = Wsk[j * 32];
                acc[0][j] += a0 * wv;
                acc[1][j] += a1 * wv;
                acc[2][j] += a2 * wv;
                acc[3][j] += a3 * wv;
            }
        }
        __syncthreads();
    }

    // Per-thread column params (cols tx + 32*j)
    float bj[8], gj[8], btj[8];
    #pragma unroll
    for (int j = 0; j < 8; j++) {
        int c = tx + 32 * j;
        bj[j]  = bias[c];
        gj[j]  = gamma[c];
        btj[j] = beta[c];
    }

    int rbase = row0 + ty * 4;
    #pragma unroll
    for (int i = 0; i < 4; i++) {
        int row = rbase + i;
        float s = 0.0f, q = 0.0f;
        #pragma unroll
        for (int j = 0; j < 8; j++) {
            float v = acc[i][j] + bj[j];
            acc[i][j] = v;
            s += v;
            q += v * v;
        }
        // warp-wide reduce (each warp holds the whole 256-col row)
        #pragma unroll
        for (int off = 16; off > 0; off >>= 1) {
            s += __shfl_xor_sync(FULL, s, off);
            q += __shfl_xor_sync(FULL, q, off);
        }
        float mean = s * (1.0f / DIM);
        float var  = q * (1.0f / DIM) - mean * mean;
        float inv  = rsqrtf(var + LN_EPS);
        if (row < N_NODES) {
            float* orow = out + (size_t)row * DIM;
            #pragma unroll
            for (int j = 0; j < 8; j++) {
                orow[tx + 32 * j] = (acc[i][j] - mean) * inv * gj[j] + btj[j];
            }
        }
    }
}

// ---------------------------------------------------------------------------
extern "C" void kernel_launch(void* const* d_in, const int* in_sizes, int n_in,
                              void* d_out, int out_size) {
    const float* features = (const float*)d_in[0];
    const void*  neighbors = d_in[1];
    const float* iw        = (const float*)d_in[2];
    const float* W         = (const float*)d_in[3];
    const float* b         = (const float*)d_in[4];
    const float* gamma     = (const float*)d_in[5];
    const float* beta      = (const float*)d_in[6];
    float* out = (float*)d_out;

    detect_idx_kernel<<<1, 32>>>(neighbors);

    int warps_per_block = 8;  // 256 threads
    int gather_blocks = (N_NODES + warps_per_block - 1) / warps_per_block;
    gather_kernel<<<gather_blocks, 256>>>((const float4*)features, neighbors, iw);

    int gemm_blocks = (N_NODES + MT - 1) / MT;
    gemm_ln_kernel<<<gemm_blocks, 256>>>(W, b, gamma, beta, out);
}

// round 5
// speedup vs baseline: 1.2742x; 1.2742x over previous
#include <cuda_runtime.h>
#include <cuda_bf16.h>

#define N_NODES 50000
#define KNB 16
#define DIM 256
#define LN_EPS 1e-5f
#define MT 64
#define KB 32

typedef unsigned long long ull;

#define FMA_F32X2(d, a, b, c) \
    asm("fma.rn.f32x2 %0, %1, %2, %3;" : "=l"(d) : "l"(a), "l"(b), "l"(c))
#define PACK_DUP(d, x) \
    asm("mov.b64 %0, {%1, %1};" : "=l"(d) : "f"(x))
#define UNPACK_F32X2(lo, hi, v) \
    asm("mov.b64 {%0, %1}, %2;" : "=f"(lo), "=f"(hi) : "l"(v))

// ---------------------------------------------------------------------------
// Fused: weighted-gather (into smem A tile) + GEMM (f32x2 packed FMA) +
// bias + LayerNorm. One block = 64 nodes. 256 threads.
//   warp ty owns rows ty*8 .. ty*8+7 (gather AND compute AND LN) -> LN is a
//   pure warp shuffle reduce over the 256-col row held in that warp's regs.
//   thread tx owns column pairs c = 2*tx + 64*j, j=0..3 (8 cols as 4 f32x2).
// ---------------------------------------------------------------------------
__global__ __launch_bounds__(256, 2) void fused_agg_kernel(
    const float4* __restrict__ feats,   // [N, DIM/4]
    const void*   __restrict__ nbr,     // [N, K] int32 or int64
    const float*  __restrict__ iw,      // [N, K]
    const float*  __restrict__ W,       // [DIM, DIM]
    const float*  __restrict__ bias,    // [DIM]
    const float*  __restrict__ gamma,   // [DIM]
    const float*  __restrict__ beta,    // [DIM]
    float* __restrict__ out)            // [N, DIM]
{
    extern __shared__ float smem[];
    float* As = smem;              // [MT][DIM]   64 KB
    float* Ws = smem + MT * DIM;   // [KB][DIM]   32 KB

    const unsigned FULL = 0xFFFFFFFFu;
    int tid = threadIdx.x;
    int tx  = tid & 31;
    int ty  = tid >> 5;
    int row0 = blockIdx.x * MT;

    // --- int64-vs-int32 detection (per block, consistent across warps) ---
    // Read 8 u64 words at a byte offset valid under the SMALLER (int32)
    // interpretation. If genuinely int64, all words are indices < N.
    // If int32, high halves are neighbor indices (nonzero w.p. ~1-2e-5 each).
    int okbit = 1;
    {
        const ull* pw = (const ull*)nbr;
        if (tx < 8) okbit = (pw[(size_t)row0 * (KNB / 2) + tx] < (ull)N_NODES);
    }
    int is64 = (__ballot_sync(FULL, okbit) == FULL);

    // ---------------- Phase 1: weighted gather into As ----------------
    for (int i = 0; i < 8; i++) {
        int lr = ty * 8 + i;
        int node = row0 + lr;
        float wv = 0.0f;
        int idx = 0;
        if (node < N_NODES && tx < KNB) {
            wv = iw[(size_t)node * KNB + tx];
            if (is64) idx = (int)(((const long long*)nbr)[(size_t)node * KNB + tx]);
            else      idx = ((const int*)nbr)[(size_t)node * KNB + tx];
        }
        float ws = wv;
        ws += __shfl_xor_sync(FULL, ws, 1);
        ws += __shfl_xor_sync(FULL, ws, 2);
        ws += __shfl_xor_sync(FULL, ws, 4);
        ws += __shfl_xor_sync(FULL, ws, 8);
        ws  = __shfl_sync(FULL, ws, 0);
        float nw = (ws == 0.0f) ? (1.0f / (float)KNB) : (wv / ws);

        float4 a0 = make_float4(0.f, 0.f, 0.f, 0.f);
        float4 a1 = make_float4(0.f, 0.f, 0.f, 0.f);
        if (node < N_NODES) {
            #pragma unroll
            for (int k = 0; k < KNB; k++) {
                int   ik = __shfl_sync(FULL, idx, k);
                float wk = __shfl_sync(FULL, nw,  k);
                const float4* r = feats + (size_t)ik * (DIM / 4);
                float4 f0 = r[tx];
                float4 f1 = r[tx + 32];
                a0.x += wk * f0.x; a0.y += wk * f0.y;
                a0.z += wk * f0.z; a0.w += wk * f0.w;
                a1.x += wk * f1.x; a1.y += wk * f1.y;
                a1.z += wk * f1.z; a1.w += wk * f1.w;
            }
        }
        ((float4*)As)[lr * (DIM / 4) + tx]      = a0;
        ((float4*)As)[lr * (DIM / 4) + tx + 32] = a1;
    }
    __syncthreads();   // As complete

    // ---------------- Phase 2: GEMM with packed f32x2 FMA ----------------
    ull acc2[8][4];
    #pragma unroll
    for (int i = 0; i < 8; i++)
        #pragma unroll
        for (int j = 0; j < 4; j++) acc2[i][j] = 0ull;

    for (int k0 = 0; k0 < DIM; k0 += KB) {
        if (k0) __syncthreads();   // previous chunk's compute done
        // Stage W chunk [KB][DIM]: 2048 float4, 8 per thread, coalesced.
        #pragma unroll
        for (int i = 0; i < 8; i++) {
            int li = tid + i * 256;
            ((float4*)Ws)[li] = ((const float4*)W)[(size_t)k0 * (DIM / 4) + li];
        }
        __syncthreads();

        const float* Asr = &As[(ty * 8) * DIM + k0];
        #pragma unroll 4
        for (int kk = 0; kk < KB; kk++) {
            // W pairs for this kk: cols (2tx+64j, 2tx+64j+1) -> LDS.64
            ull wp[4];
            const ull* wsk = (const ull*)&Ws[kk * DIM];
            #pragma unroll
            for (int j = 0; j < 4; j++) wp[j] = wsk[tx + 32 * j];
            #pragma unroll
            for (int i = 0; i < 8; i++) {
                float a = Asr[i * DIM + kk];   // broadcast LDS
                ull ap;
                PACK_DUP(ap, a);
                #pragma unroll
                for (int j = 0; j < 4; j++)
                    FMA_F32X2(acc2[i][j], ap, wp[j], acc2[i][j]);
            }
        }
    }

    // ---------------- Phase 3: bias + LayerNorm + store ----------------
    float bj[8], gj[8], btj[8];
    #pragma unroll
    for (int j = 0; j < 4; j++) {
        float2 bb = ((const float2*)bias)[tx + 32 * j];
        float2 gg = ((const float2*)gamma)[tx + 32 * j];
        float2 be = ((const float2*)beta)[tx + 32 * j];
        bj[2*j] = bb.x;  bj[2*j+1] = bb.y;
        gj[2*j] = gg.x;  gj[2*j+1] = gg.y;
        btj[2*j] = be.x; btj[2*j+1] = be.y;
    }

    int nodebase = row0 + ty * 8;
    #pragma unroll
    for (int i = 0; i < 8; i++) {
        float v[8];
        #pragma unroll
        for (int j = 0; j < 4; j++) {
            float lo, hi;
            UNPACK_F32X2(lo, hi, acc2[i][j]);
            v[2*j]   = lo + bj[2*j];
            v[2*j+1] = hi + bj[2*j+1];
        }
        float s = 0.0f, q = 0.0f;
        #pragma unroll
        for (int jj = 0; jj < 8; jj++) { s += v[jj]; q += v[jj] * v[jj]; }
        #pragma unroll
        for (int off = 16; off > 0; off >>= 1) {
            s += __shfl_xor_sync(FULL, s, off);
            q += __shfl_xor_sync(FULL, q, off);
        }
        float mean = s * (1.0f / DIM);
        float var  = q * (1.0f / DIM) - mean * mean;
        float inv  = rsqrtf(var + LN_EPS);
        int row = nodebase + i;
        if (row < N_NODES) {
            float2* orow = (float2*)(out + (size_t)row * DIM);
            #pragma unroll
            for (int j = 0; j < 4; j++) {
                float2 o;
                o.x = (v[2*j]   - mean) * inv * gj[2*j]   + btj[2*j];
                o.y = (v[2*j+1] - mean) * inv * gj[2*j+1] + btj[2*j+1];
                orow[tx + 32 * j] = o;
            }
        }
    }
}

// ---------------------------------------------------------------------------
extern "C" void kernel_launch(void* const* d_in, const int* in_sizes, int n_in,
                              void* d_out, int out_size) {
    const float* features  = (const float*)d_in[0];
    const void*  neighbors = d_in[1];
    const float* iw        = (const float*)d_in[2];
    const float* W         = (const float*)d_in[3];
    const float* b         = (const float*)d_in[4];
    const float* gamma     = (const float*)d_in[5];
    const float* beta      = (const float*)d_in[6];
    float* out = (float*)d_out;

    const int SMEM_BYTES = (MT * DIM + KB * DIM) * (int)sizeof(float);  // 96 KB
    static int attr_set = 0;
    if (!attr_set) {
        cudaFuncSetAttribute(fused_agg_kernel,
                             cudaFuncAttributeMaxDynamicSharedMemorySize,
                             SMEM_BYTES);
        attr_set = 1;
    }

    int blocks = (N_NODES + MT - 1) / MT;   // 782
    fused_agg_kernel<<<blocks, 256, SMEM_BYTES>>>(
        (const float4*)features, neighbors, iw, W, b, gamma, beta, out);
}

// round 7
// speedup vs baseline: 1.7111x; 1.3428x over previous
#include <cuda_runtime.h>
#include <cuda_bf16.h>
#include <cstdint>

#define N_NODES 50000
#define KNB 16
#define DIM 256
#define LN_EPS 1e-5f
#define MT 64
#define THREADS 256
#define KC 32                 // k per staged W chunk
#define NUM_KC (DIM / KC)     // 8

typedef unsigned long long ull;

// ---- smem layout (bytes); A stride 264 bf16 = 528 B, W chunk stride 40 bf16 = 80 B
#define A_STRIDE_B 528
#define W_STRIDE_B 80
#define SM_BIAS   0
#define SM_GAMMA  1024
#define SM_BETA   2048
#define SM_PS     3072                 // [64][4] float
#define SM_PQ     4096
#define SM_AHI    5120                 // 64 x 264 bf16 = 33792 B
#define SM_ALO    (SM_AHI + 33792)
#define SM_WHI    (SM_ALO + 33792)     // 256 x 40 bf16 = 20480 B
#define SM_WLO    (SM_WHI + 20480)
#define SM_TOTAL  (SM_WLO + 20480)     // 113664 B -> 2 CTAs/SM

// bf16 hi/lo of W^T ([n][k] row-major, stride DIM), built once per launch
__device__ __nv_bfloat16 g_wt_hi[DIM * DIM];
__device__ __nv_bfloat16 g_wt_lo[DIM * DIM];

// m16n8k16 row.col bf16 -> f32 accumulate
__device__ __forceinline__ void mma_bf16(float* d, const uint32_t* a,
                                         const uint32_t* b) {
    asm volatile(
        "mma.sync.aligned.m16n8k16.row.col.f32.bf16.bf16.f32 "
        "{%0,%1,%2,%3}, {%4,%5,%6,%7}, {%8,%9}, {%0,%1,%2,%3};"
        : "+f"(d[0]), "+f"(d[1]), "+f"(d[2]), "+f"(d[3])
        : "r"(a[0]), "r"(a[1]), "r"(a[2]), "r"(a[3]), "r"(b[0]), "r"(b[1]));
}

// ---------------------------------------------------------------------------
// One-time W transform: W[k][n] fp32 -> W^T hi/lo bf16 [n][k]
// ---------------------------------------------------------------------------
__global__ void convert_w_kernel(const float* __restrict__ W) {
    int i = blockIdx.x * blockDim.x + threadIdx.x;   // 0..65535
    int k = i >> 8, n = i & 255;
    float v = W[(size_t)k * DIM + n];
    __nv_bfloat16 h = __float2bfloat16_rn(v);
    float r = v - __bfloat162float(h);
    g_wt_hi[n * DIM + k] = h;
    g_wt_lo[n * DIM + k] = __float2bfloat16_rn(r);
}

// pack 4 floats' bf16 hi parts and lo parts; store 8B each
__device__ __forceinline__ void store_split4(char* smem, int row, int colb4,
                                             float4 v) {
    __nv_bfloat16 h0 = __float2bfloat16_rn(v.x);
    __nv_bfloat16 h1 = __float2bfloat16_rn(v.y);
    __nv_bfloat16 h2 = __float2bfloat16_rn(v.z);
    __nv_bfloat16 h3 = __float2bfloat16_rn(v.w);
    __nv_bfloat16 l0 = __float2bfloat16_rn(v.x - __bfloat162float(h0));
    __nv_bfloat16 l1 = __float2bfloat16_rn(v.y - __bfloat162float(h1));
    __nv_bfloat16 l2 = __float2bfloat16_rn(v.z - __bfloat162float(h2));
    __nv_bfloat16 l3 = __float2bfloat16_rn(v.w - __bfloat162float(h3));
    ull hv = (ull)__bfloat16_as_ushort(h0) | ((ull)__bfloat16_as_ushort(h1) << 16)
           | ((ull)__bfloat16_as_ushort(h2) << 32) | ((ull)__bfloat16_as_ushort(h3) << 48);
    ull lv = (ull)__bfloat16_as_ushort(l0) | ((ull)__bfloat16_as_ushort(l1) << 16)
           | ((ull)__bfloat16_as_ushort(l2) << 32) | ((ull)__bfloat16_as_ushort(l3) << 48);
    size_t off = (size_t)row * A_STRIDE_B + (size_t)colb4 * 8;
    *(ull*)(smem + SM_AHI + off) = hv;
    *(ull*)(smem + SM_ALO + off) = lv;
}

// ---------------------------------------------------------------------------
// Fused: gather -> bf16 hi/lo split -> mma.sync 3-term GEMM -> bias + LN.
// 256 threads (8 warps). Warp grid 2(M) x 4(N); warp tile 32 x 64.
// ---------------------------------------------------------------------------
__global__ __launch_bounds__(THREADS, 2) void fused_mma_kernel(
    const float4* __restrict__ feats,
    const void*   __restrict__ nbr,
    const float*  __restrict__ iw,
    const float*  __restrict__ bias,
    const float*  __restrict__ gamma,
    const float*  __restrict__ beta,
    float* __restrict__ out)
{
    extern __shared__ char smem[];
    const unsigned FULL = 0xFFFFFFFFu;
    int tid = threadIdx.x;
    int tx  = tid & 31;
    int wid = tid >> 5;
    int row0 = blockIdx.x * MT;

    int g = tx >> 2;          // fragment group (0..7)
    int t = tx & 3;           // thread-in-group
    int warpM = wid >> 2;     // 0..1
    int warpN = wid & 3;      // 0..3
    int mrow = warpM * 32;
    int n0   = warpN * 64;

    if (tid < 256) {
        ((float*)(smem + SM_BIAS))[tid]  = bias[tid];
        ((float*)(smem + SM_GAMMA))[tid] = gamma[tid];
        ((float*)(smem + SM_BETA))[tid]  = beta[tid];
    }

    // ---- int64-vs-int32 detection (offset valid under both interpretations)
    int okbit = 1;
    {
        const ull* pw = (const ull*)nbr;
        if (tx < 8) okbit = (pw[(size_t)row0 * (KNB / 2) + tx] < (ull)N_NODES);
    }
    int is64 = (__ballot_sync(FULL, okbit) == FULL);

    // ---------------- Phase 1: weighted gather, split to bf16 hi/lo ------
    #pragma unroll 1
    for (int i = 0; i < 8; i++) {
        int lr = wid * 8 + i;
        int node = row0 + lr;
        float wv = 0.0f;
        int idx = 0;
        if (node < N_NODES && tx < KNB) {
            wv = iw[(size_t)node * KNB + tx];
            if (is64) idx = (int)(((const long long*)nbr)[(size_t)node * KNB + tx]);
            else      idx = ((const int*)nbr)[(size_t)node * KNB + tx];
        }
        float ws = wv;
        ws += __shfl_xor_sync(FULL, ws, 1);
        ws += __shfl_xor_sync(FULL, ws, 2);
        ws += __shfl_xor_sync(FULL, ws, 4);
        ws += __shfl_xor_sync(FULL, ws, 8);
        ws  = __shfl_sync(FULL, ws, 0);
        float nw = (ws == 0.0f) ? (1.0f / (float)KNB) : (wv / ws);

        float4 a0 = make_float4(0.f, 0.f, 0.f, 0.f);
        float4 a1 = make_float4(0.f, 0.f, 0.f, 0.f);
        if (node < N_NODES) {
            #pragma unroll
            for (int k = 0; k < KNB; k++) {
                int   ik = __shfl_sync(FULL, idx, k);
                float wk = __shfl_sync(FULL, nw,  k);
                const float4* r = feats + (size_t)ik * (DIM / 4);
                float4 f0 = r[tx];
                float4 f1 = r[tx + 32];
                a0.x += wk * f0.x; a0.y += wk * f0.y;
                a0.z += wk * f0.z; a0.w += wk * f0.w;
                a1.x += wk * f1.x; a1.y += wk * f1.y;
                a1.z += wk * f1.z; a1.w += wk * f1.w;
            }
        }
        store_split4(smem, lr, tx, a0);        // cols 4tx..4tx+3
        store_split4(smem, lr, tx + 32, a1);   // cols 128+4tx..
    }

    // ---------------- Phase 2: 3-term bf16 split GEMM via mma.sync -------
    float d[2][8][4];
    #pragma unroll
    for (int mi = 0; mi < 2; mi++)
        #pragma unroll
        for (int ni = 0; ni < 8; ni++)
            #pragma unroll
            for (int j = 0; j < 4; j++) d[mi][ni][j] = 0.0f;

    for (int kc = 0; kc < NUM_KC; kc++) {
        __syncthreads();   // A ready (kc==0) / previous chunk compute done
        // stage W^T hi/lo chunk [256 n][KC k], padded stride 40 bf16
        #pragma unroll
        for (int u = 0; u < 4; u++) {
            int li = tid + u * THREADS;      // 0..1023
            int n = li >> 2, uk = li & 3;
            size_t doff = (size_t)n * W_STRIDE_B + uk * 16;
            *(uint4*)(smem + SM_WHI + doff) =
                *(const uint4*)&g_wt_hi[n * DIM + kc * KC + uk * 8];
            *(uint4*)(smem + SM_WLO + doff) =
                *(const uint4*)&g_wt_lo[n * DIM + kc * KC + uk * 8];
        }
        __syncthreads();

        #pragma unroll
        for (int k16 = 0; k16 < KC / 16; k16++) {
            // B fragments: b0: k=2t..2t+1, b1: k=2t+8..2t+9, n = n0+8ni+g
            uint32_t bh[8][2], bl[8][2];
            int kbyteW = (k16 * 16 + 2 * t) * 2;
            #pragma unroll
            for (int ni = 0; ni < 8; ni++) {
                size_t bb = (size_t)(n0 + ni * 8 + g) * W_STRIDE_B + kbyteW;
                bh[ni][0] = *(const uint32_t*)(smem + SM_WHI + bb);
                bh[ni][1] = *(const uint32_t*)(smem + SM_WHI + bb + 16);
                bl[ni][0] = *(const uint32_t*)(smem + SM_WLO + bb);
                bl[ni][1] = *(const uint32_t*)(smem + SM_WLO + bb + 16);
            }
            int kbyteA = (kc * KC + k16 * 16 + 2 * t) * 2;
            #pragma unroll
            for (int mi = 0; mi < 2; mi++) {
                int rr = mrow + mi * 16 + g;
                size_t ab0 = (size_t)rr * A_STRIDE_B + kbyteA;
                size_t ab1 = (size_t)(rr + 8) * A_STRIDE_B + kbyteA;
                uint32_t ah[4], al[4];
                ah[0] = *(const uint32_t*)(smem + SM_AHI + ab0);
                ah[1] = *(const uint32_t*)(smem + SM_AHI + ab1);
                ah[2] = *(const uint32_t*)(smem + SM_AHI + ab0 + 16);
                ah[3] = *(const uint32_t*)(smem + SM_AHI + ab1 + 16);
                al[0] = *(const uint32_t*)(smem + SM_ALO + ab0);
                al[1] = *(const uint32_t*)(smem + SM_ALO + ab1);
                al[2] = *(const uint32_t*)(smem + SM_ALO + ab0 + 16);
                al[3] = *(const uint32_t*)(smem + SM_ALO + ab1 + 16);
                #pragma unroll
                for (int ni = 0; ni < 8; ni++) {
                    mma_bf16(d[mi][ni], ah, bh[ni]);
                    mma_bf16(d[mi][ni], al, bh[ni]);
                    mma_bf16(d[mi][ni], ah, bl[ni]);
                }
            }
        }
    }

    // ---------------- Phase 3: bias + LayerNorm + store ------------------
    const float* bias_s  = (const float*)(smem + SM_BIAS);
    const float* gamma_s = (const float*)(smem + SM_GAMMA);
    const float* beta_s  = (const float*)(smem + SM_BETA);
    float* ps = (float*)(smem + SM_PS);
    float* pq = (float*)(smem + SM_PQ);

    // add bias; per-thread partial sums for the 4 rows this thread touches
    float v[2][8][4];
    float s[2][2], q[2][2];   // [mi][half]
    #pragma unroll
    for (int mi = 0; mi < 2; mi++) { s[mi][0]=s[mi][1]=q[mi][0]=q[mi][1]=0.f; }
    #pragma unroll
    for (int mi = 0; mi < 2; mi++)
        #pragma unroll
        for (int ni = 0; ni < 8; ni++) {
            int c0 = n0 + ni * 8 + 2 * t;
            float b0 = bias_s[c0], b1 = bias_s[c0 + 1];
            float x;
            x = d[mi][ni][0] + b0; v[mi][ni][0] = x; s[mi][0] += x; q[mi][0] += x * x;
            x = d[mi][ni][1] + b1; v[mi][ni][1] = x; s[mi][0] += x; q[mi][0] += x * x;
            x = d[mi][ni][2] + b0; v[mi][ni][2] = x; s[mi][1] += x; q[mi][1] += x * x;
            x = d[mi][ni][3] + b1; v[mi][ni][3] = x; s[mi][1] += x; q[mi][1] += x * x;
        }
    // quad reduce over t (lanes g*4..g*4+3 share rows)
    #pragma unroll
    for (int mi = 0; mi < 2; mi++)
        #pragma unroll
        for (int h = 0; h < 2; h++) {
            s[mi][h] += __shfl_xor_sync(FULL, s[mi][h], 1);
            s[mi][h] += __shfl_xor_sync(FULL, s[mi][h], 2);
            q[mi][h] += __shfl_xor_sync(FULL, q[mi][h], 1);
            q[mi][h] += __shfl_xor_sync(FULL, q[mi][h], 2);
        }
    if (t == 0) {
        #pragma unroll
        for (int mi = 0; mi < 2; mi++)
            #pragma unroll
            for (int h = 0; h < 2; h++) {
                int r = mrow + mi * 16 + g + 8 * h;
                ps[r * 4 + warpN] = s[mi][h];
                pq[r * 4 + warpN] = q[mi][h];
            }
    }
    __syncthreads();

    #pragma unroll
    for (int mi = 0; mi < 2; mi++)
        #pragma unroll
        for (int h = 0; h < 2; h++) {
            int r = mrow + mi * 16 + g + 8 * h;
            float st = ps[r*4+0] + ps[r*4+1] + ps[r*4+2] + ps[r*4+3];
            float qt = pq[r*4+0] + pq[r*4+1] + pq[r*4+2] + pq[r*4+3];
            float mean = st * (1.0f / DIM);
            float var  = qt * (1.0f / DIM) - mean * mean;
            float inv  = rsqrtf(var + LN_EPS);
            int node = row0 + r;
            if (node < N_NODES) {
                float* orow = out + (size_t)node * DIM;
                #pragma unroll
                for (int ni = 0; ni < 8; ni++) {
                    int c0 = n0 + ni * 8 + 2 * t;
                    float2 o;
                    float vv0 = v[mi][ni][h ? 2 : 0];
                    float vv1 = v[mi][ni][h ? 3 : 1];
                    o.x = (vv0 - mean) * inv * gamma_s[c0]     + beta_s[c0];
                    o.y = (vv1 - mean) * inv * gamma_s[c0 + 1] + beta_s[c0 + 1];
                    *(float2*)(orow + c0) = o;
                }
            }
        }
}

// ---------------------------------------------------------------------------
extern "C" void kernel_launch(void* const* d_in, const int* in_sizes, int n_in,
                              void* d_out, int out_size) {
    const float* features  = (const float*)d_in[0];
    const void*  neighbors = d_in[1];
    const float* iw        = (const float*)d_in[2];
    const float* W         = (const float*)d_in[3];
    const float* b         = (const float*)d_in[4];
    const float* gamma     = (const float*)d_in[5];
    const float* beta      = (const float*)d_in[6];
    float* out = (float*)d_out;

    cudaFuncSetAttribute(fused_mma_kernel,
                         cudaFuncAttributeMaxDynamicSharedMemorySize, SM_TOTAL);

    convert_w_kernel<<<DIM * DIM / 256, 256>>>(W);

    int blocks = (N_NODES + MT - 1) / MT;   // 782
    fused_mma_kernel<<<blocks, THREADS, SM_TOTAL>>>(
        (const float4*)features, neighbors, iw, b, gamma, beta, out);
}

// round 11
// speedup vs baseline: 1.9508x; 1.1401x over previous
#include <cuda_runtime.h>
#include <cuda_bf16.h>
#include <cstdint>

#define N_NODES 50000
#define KNB 16
#define DIM 256
#define LN_EPS 1e-5f
#define MT 64
#define THREADS 256
#define KC 16                 // k per staged W chunk
#define NUM_KC (DIM / KC)     // 16

typedef unsigned long long ull;

// ---- smem layout (bytes)
#define A_STRIDE_B 528        // 264 bf16 (256 data + 8 pad): rows at 16*i mod 128
#define W_STRIDE_B 48         // 24 bf16 (16 data + 8 pad): rows at {0,48,96,16,64,112,32,80}
#define SM_BIAS   0
#define SM_GAMMA  1024
#define SM_BETA   2048
#define SM_PS     3072                 // [64][4] float
#define SM_PQ     4096
#define SM_AHI    5120                 // 64 x 528 B = 33792
#define SM_ALO    (SM_AHI + 33792)
#define SM_WHI    (SM_ALO + 33792)     // 256 x 48 B = 12288
#define SM_WLO    (SM_WHI + 12288)
#define SM_TOTAL  (SM_WLO + 12288)     // 97280 B -> 2 CTAs/SM

// bf16 hi/lo of W^T ([n][k] row-major, stride DIM), built once per launch
__device__ __nv_bfloat16 g_wt_hi[DIM * DIM];
__device__ __nv_bfloat16 g_wt_lo[DIM * DIM];

__device__ __forceinline__ uint32_t smem_u32(const void* p) {
    uint32_t a;
    asm("{ .reg .u64 t; cvta.to.shared.u64 t, %1; cvt.u32.u64 %0, t; }"
        : "=r"(a) : "l"(p));
    return a;
}

// m16n8k16 row.col bf16 -> f32 accumulate
__device__ __forceinline__ void mma_bf16(float* d, const uint32_t* a,
                                         const uint32_t* b) {
    asm volatile(
        "mma.sync.aligned.m16n8k16.row.col.f32.bf16.bf16.f32 "
        "{%0,%1,%2,%3}, {%4,%5,%6,%7}, {%8,%9}, {%0,%1,%2,%3};"
        : "+f"(d[0]), "+f"(d[1]), "+f"(d[2]), "+f"(d[3])
        : "r"(a[0]), "r"(a[1]), "r"(a[2]), "r"(a[3]), "r"(b[0]), "r"(b[1]));
}

__device__ __forceinline__ void ldmx4(uint32_t* r, uint32_t addr) {
    asm volatile("ldmatrix.sync.aligned.m8n8.x4.shared.b16 {%0,%1,%2,%3}, [%4];"
        : "=r"(r[0]), "=r"(r[1]), "=r"(r[2]), "=r"(r[3]) : "r"(addr));
}

// ---------------------------------------------------------------------------
// One-time W transform: W[k][n] fp32 -> W^T hi/lo bf16 [n][k]
// ---------------------------------------------------------------------------
__global__ void convert_w_kernel(const float* __restrict__ W) {
    int i = blockIdx.x * blockDim.x + threadIdx.x;   // 0..65535
    int k = i >> 8, n = i & 255;
    float v = W[(size_t)k * DIM + n];
    __nv_bfloat16 h = __float2bfloat16_rn(v);
    float r = v - __bfloat162float(h);
    g_wt_hi[n * DIM + k] = h;
    g_wt_lo[n * DIM + k] = __float2bfloat16_rn(r);
}

// pack 4 floats' bf16 hi parts and lo parts; store 8B each table
__device__ __forceinline__ void store_split4(char* smem, int row, int colb4,
                                             float4 v) {
    __nv_bfloat16 h0 = __float2bfloat16_rn(v.x);
    __nv_bfloat16 h1 = __float2bfloat16_rn(v.y);
    __nv_bfloat16 h2 = __float2bfloat16_rn(v.z);
    __nv_bfloat16 h3 = __float2bfloat16_rn(v.w);
    __nv_bfloat16 l0 = __float2bfloat16_rn(v.x - __bfloat162float(h0));
    __nv_bfloat16 l1 = __float2bfloat16_rn(v.y - __bfloat162float(h1));
    __nv_bfloat16 l2 = __float2bfloat16_rn(v.z - __bfloat162float(h2));
    __nv_bfloat16 l3 = __float2bfloat16_rn(v.w - __bfloat162float(h3));
    ull hv = (ull)__bfloat16_as_ushort(h0) | ((ull)__bfloat16_as_ushort(h1) << 16)
           | ((ull)__bfloat16_as_ushort(h2) << 32) | ((ull)__bfloat16_as_ushort(h3) << 48);
    ull lv = (ull)__bfloat16_as_ushort(l0) | ((ull)__bfloat16_as_ushort(l1) << 16)
           | ((ull)__bfloat16_as_ushort(l2) << 32) | ((ull)__bfloat16_as_ushort(l3) << 48);
    size_t off = (size_t)row * A_STRIDE_B + (size_t)colb4 * 8;
    *(ull*)(smem + SM_AHI + off) = hv;
    *(ull*)(smem + SM_ALO + off) = lv;
}

// ---------------------------------------------------------------------------
// Fused: gather -> bf16 hi/lo split -> ldmatrix + mma.sync 3-term GEMM ->
// bias + LayerNorm. 256 threads (8 warps). Warp grid 2(M) x 4(N).
// ---------------------------------------------------------------------------
__global__ __launch_bounds__(THREADS, 2) void fused_mma_kernel(
    const float4* __restrict__ feats,
    const void*   __restrict__ nbr,
    const float*  __restrict__ iw,
    const float*  __restrict__ bias,
    const float*  __restrict__ gamma,
    const float*  __restrict__ beta,
    float* __restrict__ out)
{
    extern __shared__ char smem[];
    uint32_t sb = smem_u32(smem);
    const unsigned FULL = 0xFFFFFFFFu;
    int tid = threadIdx.x;
    int tx  = tid & 31;
    int wid = tid >> 5;
    int row0 = blockIdx.x * MT;

    int g = tx >> 2;          // fragment group (0..7)
    int t = tx & 3;           // thread-in-group
    int warpM = wid >> 2;     // 0..1
    int warpN = wid & 3;      // 0..3
    int mrow = warpM * 32;
    int n0   = warpN * 64;

    ((float*)(smem + SM_BIAS))[tid]  = bias[tid];
    ((float*)(smem + SM_GAMMA))[tid] = gamma[tid];
    ((float*)(smem + SM_BETA))[tid]  = beta[tid];

    // ---- int64-vs-int32 detection (offset valid under both interpretations)
    int okbit = 1;
    {
        const ull* pw = (const ull*)nbr;
        if (tx < 8) okbit = (pw[(size_t)row0 * (KNB / 2) + tx] < (ull)N_NODES);
    }
    int is64 = (__ballot_sync(FULL, okbit) == FULL);

    // ---------------- Phase 1: weighted gather (2 rows in flight) --------
    #pragma unroll 1
    for (int i = 0; i < 8; i += 2) {
        int lr0 = wid * 8 + i;
        int lr1 = lr0 + 1;
        int node0 = row0 + lr0, node1 = row0 + lr1;
        float wv0 = 0.f, wv1 = 0.f;
        int idx0 = 0, idx1 = 0;
        if (tx < KNB) {
            if (node0 < N_NODES) {
                wv0 = iw[(size_t)node0 * KNB + tx];
                if (is64) idx0 = (int)(((const long long*)nbr)[(size_t)node0 * KNB + tx]);
                else      idx0 = ((const int*)nbr)[(size_t)node0 * KNB + tx];
            }
            if (node1 < N_NODES) {
                wv1 = iw[(size_t)node1 * KNB + tx];
                if (is64) idx1 = (int)(((const long long*)nbr)[(size_t)node1 * KNB + tx]);
                else      idx1 = ((const int*)nbr)[(size_t)node1 * KNB + tx];
            }
        }
        float ws0 = wv0, ws1 = wv1;
        #pragma unroll
        for (int o = 1; o < 16; o <<= 1) {
            ws0 += __shfl_xor_sync(FULL, ws0, o);
            ws1 += __shfl_xor_sync(FULL, ws1, o);
        }
        ws0 = __shfl_sync(FULL, ws0, 0);
        ws1 = __shfl_sync(FULL, ws1, 0);
        float nw0 = (ws0 == 0.0f) ? (1.0f / (float)KNB) : (wv0 / ws0);
        float nw1 = (ws1 == 0.0f) ? (1.0f / (float)KNB) : (wv1 / ws1);

        float4 a00 = make_float4(0.f,0.f,0.f,0.f), a01 = a00;
        float4 a10 = a00, a11 = a00;
        #pragma unroll
        for (int k = 0; k < KNB; k++) {
            int   ik0 = __shfl_sync(FULL, idx0, k);
            float wk0 = __shfl_sync(FULL, nw0,  k);
            int   ik1 = __shfl_sync(FULL, idx1, k);
            float wk1 = __shfl_sync(FULL, nw1,  k);
            const float4* r0 = feats + (size_t)ik0 * (DIM / 4);
            const float4* r1 = feats + (size_t)ik1 * (DIM / 4);
            float4 f00 = r0[tx];
            float4 f01 = r0[tx + 32];
            float4 f10 = r1[tx];
            float4 f11 = r1[tx + 32];
            a00.x += wk0*f00.x; a00.y += wk0*f00.y; a00.z += wk0*f00.z; a00.w += wk0*f00.w;
            a01.x += wk0*f01.x; a01.y += wk0*f01.y; a01.z += wk0*f01.z; a01.w += wk0*f01.w;
            a10.x += wk1*f10.x; a10.y += wk1*f10.y; a10.z += wk1*f10.z; a10.w += wk1*f10.w;
            a11.x += wk1*f11.x; a11.y += wk1*f11.y; a11.z += wk1*f11.z; a11.w += wk1*f11.w;
        }
        store_split4(smem, lr0, tx, a00);
        store_split4(smem, lr0, tx + 32, a01);
        store_split4(smem, lr1, tx, a10);
        store_split4(smem, lr1, tx + 32, a11);
    }

    // ---------------- Phase 2: 3-term bf16 split GEMM --------------------
    float d[2][8][4];
    #pragma unroll
    for (int mi = 0; mi < 2; mi++)
        #pragma unroll
        for (int ni = 0; ni < 8; ni++)
            #pragma unroll
            for (int j = 0; j < 4; j++) d[mi][ni][j] = 0.0f;

    // lane-dependent ldmatrix offsets
    uint32_t a_lane = (uint32_t)((((tx >> 3) & 1) * 8 + (tx & 7)) * A_STRIDE_B
                                 + (tx >> 4) * 16);
    uint32_t b_lane = (uint32_t)(((((tx >> 4) & 1) * 8) + (tx & 7)) * W_STRIDE_B
                                 + ((tx >> 3) & 1) * 16);
    uint32_t a_hi = sb + SM_AHI + a_lane + (uint32_t)mrow * A_STRIDE_B;
    uint32_t a_lo = sb + SM_ALO + a_lane + (uint32_t)mrow * A_STRIDE_B;
    uint32_t b_hi = sb + SM_WHI + b_lane + (uint32_t)n0 * W_STRIDE_B;
    uint32_t b_lo = sb + SM_WLO + b_lane + (uint32_t)n0 * W_STRIDE_B;

    // W chunk prefetch registers (chunk 0)
    uint4 ph[2], pl[2];
    {
        #pragma unroll
        for (int u = 0; u < 2; u++) {
            int li = tid + u * THREADS;       // 0..511
            int n = li >> 1, uk = li & 1;
            ph[u] = *(const uint4*)&g_wt_hi[n * DIM + uk * 8];
            pl[u] = *(const uint4*)&g_wt_lo[n * DIM + uk * 8];
        }
    }

    #pragma unroll 1
    for (int kc = 0; kc < NUM_KC; kc++) {
        __syncthreads();   // A ready (kc==0) / previous chunk compute done
        #pragma unroll
        for (int u = 0; u < 2; u++) {
            int li = tid + u * THREADS;
            int n = li >> 1, uk = li & 1;
            *(uint4*)(smem + SM_WHI + (size_t)n * W_STRIDE_B + uk * 16) = ph[u];
            *(uint4*)(smem + SM_WLO + (size_t)n * W_STRIDE_B + uk * 16) = pl[u];
        }
        __syncthreads();   // W chunk ready

        if (kc + 1 < NUM_KC) {   // prefetch next chunk (latency hidden by MMA)
            #pragma unroll
            for (int u = 0; u < 2; u++) {
                int li = tid + u * THREADS;
                int n = li >> 1, uk = li & 1;
                ph[u] = *(const uint4*)&g_wt_hi[n * DIM + (kc + 1) * KC + uk * 8];
                pl[u] = *(const uint4*)&g_wt_lo[n * DIM + (kc + 1) * KC + uk * 8];
            }
        }

        // A fragments for this 16-k chunk (hi and lo)
        uint32_t ah[2][4], al[2][4];
        uint32_t kb = (uint32_t)kc * 32;     // 16 k * 2B
        #pragma unroll
        for (int mi = 0; mi < 2; mi++) {
            ldmx4(ah[mi], a_hi + (uint32_t)mi * 16 * A_STRIDE_B + kb);
            ldmx4(al[mi], a_lo + (uint32_t)mi * 16 * A_STRIDE_B + kb);
        }
        // B fragments: 4 ni-pairs
        #pragma unroll
        for (int p = 0; p < 4; p++) {
            uint32_t bh[4], bl[4];
            ldmx4(bh, b_hi + (uint32_t)p * 16 * W_STRIDE_B);
            ldmx4(bl, b_lo + (uint32_t)p * 16 * W_STRIDE_B);
            #pragma unroll
            for (int mi = 0; mi < 2; mi++) {
                mma_bf16(d[mi][2*p],     ah[mi], bh);
                mma_bf16(d[mi][2*p],     al[mi], bh);
                mma_bf16(d[mi][2*p],     ah[mi], bl);
                mma_bf16(d[mi][2*p + 1], ah[mi], bh + 2);
                mma_bf16(d[mi][2*p + 1], al[mi], bh + 2);
                mma_bf16(d[mi][2*p + 1], ah[mi], bl + 2);
            }
        }
    }

    // ---------------- Phase 3: bias + LayerNorm + store ------------------
    const float* bias_s  = (const float*)(smem + SM_BIAS);
    const float* gamma_s = (const float*)(smem + SM_GAMMA);
    const float* beta_s  = (const float*)(smem + SM_BETA);
    float* ps = (float*)(smem + SM_PS);
    float* pq = (float*)(smem + SM_PQ);

    float v[2][8][4];
    float s[2][2], q[2][2];   // [mi][half]
    #pragma unroll
    for (int mi = 0; mi < 2; mi++) { s[mi][0]=s[mi][1]=q[mi][0]=q[mi][1]=0.f; }
    #pragma unroll
    for (int mi = 0; mi < 2; mi++)
        #pragma unroll
        for (int ni = 0; ni < 8; ni++) {
            int c0 = n0 + ni * 8 + 2 * t;
            float b0 = bias_s[c0], b1 = bias_s[c0 + 1];
            float x;
            x = d[mi][ni][0] + b0; v[mi][ni][0] = x; s[mi][0] += x; q[mi][0] += x * x;
            x = d[mi][ni][1] + b1; v[mi][ni][1] = x; s[mi][0] += x; q[mi][0] += x * x;
            x = d[mi][ni][2] + b0; v[mi][ni][2] = x; s[mi][1] += x; q[mi][1] += x * x;
            x = d[mi][ni][3] + b1; v[mi][ni][3] = x; s[mi][1] += x; q[mi][1] += x * x;
        }
    #pragma unroll
    for (int mi = 0; mi < 2; mi++)
        #pragma unroll
        for (int h = 0; h < 2; h++) {
            s[mi][h] += __shfl_xor_sync(FULL, s[mi][h], 1);
            s[mi][h] += __shfl_xor_sync(FULL, s[mi][h], 2);
            q[mi][h] += __shfl_xor_sync(FULL, q[mi][h], 1);
            q[mi][h] += __shfl_xor_sync(FULL, q[mi][h], 2);
        }
    if (t == 0) {
        #pragma unroll
        for (int mi = 0; mi < 2; mi++)
            #pragma unroll
            for (int h = 0; h < 2; h++) {
                int r = mrow + mi * 16 + g + 8 * h;
                ps[r * 4 + warpN] = s[mi][h];
                pq[r * 4 + warpN] = q[mi][h];
            }
    }
    __syncthreads();

    #pragma unroll
    for (int mi = 0; mi < 2; mi++)
        #pragma unroll
        for (int h = 0; h < 2; h++) {
            int r = mrow + mi * 16 + g + 8 * h;
            float st = ps[r*4+0] + ps[r*4+1] + ps[r*4+2] + ps[r*4+3];
            float qt = pq[r*4+0] + pq[r*4+1] + pq[r*4+2] + pq[r*4+3];
            float mean = st * (1.0f / DIM);
            float var  = qt * (1.0f / DIM) - mean * mean;
            float inv  = rsqrtf(var + LN_EPS);
            int node = row0 + r;
            if (node < N_NODES) {
                float* orow = out + (size_t)node * DIM;
                #pragma unroll
                for (int ni = 0; ni < 8; ni++) {
                    int c0 = n0 + ni * 8 + 2 * t;
                    float2 o;
                    float vv0 = v[mi][ni][h ? 2 : 0];
                    float vv1 = v[mi][ni][h ? 3 : 1];
                    o.x = (vv0 - mean) * inv * gamma_s[c0]     + beta_s[c0];
                    o.y = (vv1 - mean) * inv * gamma_s[c0 + 1] + beta_s[c0 + 1];
                    *(float2*)(orow + c0) = o;
                }
            }
        }
}

// ---------------------------------------------------------------------------
extern "C" void kernel_launch(void* const* d_in, const int* in_sizes, int n_in,
                              void* d_out, int out_size) {
    const float* features  = (const float*)d_in[0];
    const void*  neighbors = d_in[1];
    const float* iw        = (const float*)d_in[2];
    const float* W         = (const float*)d_in[3];
    const float* b         = (const float*)d_in[4];
    const float* gamma     = (const float*)d_in[5];
    const float* beta      = (const float*)d_in[6];
    float* out = (float*)d_out;

    cudaFuncSetAttribute(fused_mma_kernel,
                         cudaFuncAttributeMaxDynamicSharedMemorySize, SM_TOTAL);

    convert_w_kernel<<<DIM * DIM / 256, 256>>>(W);

    int blocks = (N_NODES + MT - 1) / MT;   // 782
    fused_mma_kernel<<<blocks, THREADS, SM_TOTAL>>>(
        (const float4*)features, neighbors, iw, b, gamma, beta, out);
}

// round 12
// speedup vs baseline: 2.4402x; 1.2509x over previous
#include <cuda_runtime.h>
#include <cuda_bf16.h>
#include <cstdint>

#define N_NODES 50000
#define KNB 16
#define DIM 256
#define LN_EPS 1e-5f
#define MT 64
#define THREADS 256
#define NUM_KC 16             // k16 chunks

typedef unsigned long long ull;

// ---- smem layout (bytes)
#define A_STRIDE_B 528        // 264 bf16 (256 data + 8 pad): rows at 16*i mod 128
#define SM_BIAS   0
#define SM_GAMMA  1024
#define SM_BETA   2048
#define SM_PS     3072                 // [64][4] float
#define SM_PQ     4096
#define SM_AHI    5120                 // 64 x 528 B = 33792
#define SM_ALO    (SM_AHI + 33792)
#define SM_TOTAL  (SM_ALO + 33792)     // 72704 B

// W in mma-fragment-linear order: [nt(32)][kc(16)][lane(32)] uint2 {b0,b1}
// b0 = pack(W[kc*16+2t][n], W[kc*16+2t+1][n]); b1 = same at k+8; n = nt*8+g.
__device__ uint2 g_wf_hi[32 * 16 * 32];
__device__ uint2 g_wf_lo[32 * 16 * 32];

__device__ __forceinline__ uint32_t smem_u32(const void* p) {
    uint32_t a;
    asm("{ .reg .u64 t; cvta.to.shared.u64 t, %1; cvt.u32.u64 %0, t; }"
        : "=r"(a) : "l"(p));
    return a;
}

// m16n8k16 row.col bf16 -> f32 accumulate
__device__ __forceinline__ void mma_bf16(float* d, const uint32_t* a,
                                         const uint32_t* b) {
    asm volatile(
        "mma.sync.aligned.m16n8k16.row.col.f32.bf16.bf16.f32 "
        "{%0,%1,%2,%3}, {%4,%5,%6,%7}, {%8,%9}, {%0,%1,%2,%3};"
        : "+f"(d[0]), "+f"(d[1]), "+f"(d[2]), "+f"(d[3])
        : "r"(a[0]), "r"(a[1]), "r"(a[2]), "r"(a[3]), "r"(b[0]), "r"(b[1]));
}

__device__ __forceinline__ void ldmx4(uint32_t* r, uint32_t addr) {
    asm volatile("ldmatrix.sync.aligned.m8n8.x4.shared.b16 {%0,%1,%2,%3}, [%4];"
        : "=r"(r[0]), "=r"(r[1]), "=r"(r[2]), "=r"(r[3]) : "r"(addr));
}

// ---------------------------------------------------------------------------
// One-time W transform: W[k][n] fp32 -> fragment-linear bf16 hi/lo tables.
// One thread per (nt, kc, lane) word pair.
// ---------------------------------------------------------------------------
__global__ void convert_w_kernel(const float* __restrict__ W) {
    int i = blockIdx.x * blockDim.x + threadIdx.x;   // 0..16383
    int lane = i & 31;
    int kc = (i >> 5) & 15;
    int nt = i >> 9;
    int g = lane >> 2, t = lane & 3;
    int n = nt * 8 + g;
    int k0 = kc * 16 + 2 * t;

    float v00 = W[(size_t)(k0)     * DIM + n];
    float v01 = W[(size_t)(k0 + 1) * DIM + n];
    float v10 = W[(size_t)(k0 + 8) * DIM + n];
    float v11 = W[(size_t)(k0 + 9) * DIM + n];

    __nv_bfloat16 h00 = __float2bfloat16_rn(v00);
    __nv_bfloat16 h01 = __float2bfloat16_rn(v01);
    __nv_bfloat16 h10 = __float2bfloat16_rn(v10);
    __nv_bfloat16 h11 = __float2bfloat16_rn(v11);
    __nv_bfloat16 l00 = __float2bfloat16_rn(v00 - __bfloat162float(h00));
    __nv_bfloat16 l01 = __float2bfloat16_rn(v01 - __bfloat162float(h01));
    __nv_bfloat16 l10 = __float2bfloat16_rn(v10 - __bfloat162float(h10));
    __nv_bfloat16 l11 = __float2bfloat16_rn(v11 - __bfloat162float(h11));

    uint2 hv, lv;
    hv.x = (uint32_t)__bfloat16_as_ushort(h00) | ((uint32_t)__bfloat16_as_ushort(h01) << 16);
    hv.y = (uint32_t)__bfloat16_as_ushort(h10) | ((uint32_t)__bfloat16_as_ushort(h11) << 16);
    lv.x = (uint32_t)__bfloat16_as_ushort(l00) | ((uint32_t)__bfloat16_as_ushort(l01) << 16);
    lv.y = (uint32_t)__bfloat16_as_ushort(l10) | ((uint32_t)__bfloat16_as_ushort(l11) << 16);
    g_wf_hi[i] = hv;
    g_wf_lo[i] = lv;
}

// pack 4 floats' bf16 hi parts and lo parts; store 8B each table
__device__ __forceinline__ void store_split4(char* smem, int row, int colb4,
                                             float4 v) {
    __nv_bfloat16 h0 = __float2bfloat16_rn(v.x);
    __nv_bfloat16 h1 = __float2bfloat16_rn(v.y);
    __nv_bfloat16 h2 = __float2bfloat16_rn(v.z);
    __nv_bfloat16 h3 = __float2bfloat16_rn(v.w);
    __nv_bfloat16 l0 = __float2bfloat16_rn(v.x - __bfloat162float(h0));
    __nv_bfloat16 l1 = __float2bfloat16_rn(v.y - __bfloat162float(h1));
    __nv_bfloat16 l2 = __float2bfloat16_rn(v.z - __bfloat162float(h2));
    __nv_bfloat16 l3 = __float2bfloat16_rn(v.w - __bfloat162float(h3));
    ull hv = (ull)__bfloat16_as_ushort(h0) | ((ull)__bfloat16_as_ushort(h1) << 16)
           | ((ull)__bfloat16_as_ushort(h2) << 32) | ((ull)__bfloat16_as_ushort(h3) << 48);
    ull lv = (ull)__bfloat16_as_ushort(l0) | ((ull)__bfloat16_as_ushort(l1) << 16)
           | ((ull)__bfloat16_as_ushort(l2) << 32) | ((ull)__bfloat16_as_ushort(l3) << 48);
    size_t off = (size_t)row * A_STRIDE_B + (size_t)colb4 * 8;
    *(ull*)(smem + SM_AHI + off) = hv;
    *(ull*)(smem + SM_ALO + off) = lv;
}

// ---------------------------------------------------------------------------
// Fused: gather -> bf16 hi/lo split -> ldmatrix-A + LDG-fragment-B mma.sync
// 3-term GEMM (barrier-free mainloop) -> bias + LayerNorm.
// 256 threads (8 warps). Warp grid 2(M) x 4(N); warp tile 32 x 64.
// ---------------------------------------------------------------------------
__global__ __launch_bounds__(THREADS, 2) void fused_mma_kernel(
    const float4* __restrict__ feats,
    const void*   __restrict__ nbr,
    const float*  __restrict__ iw,
    const float*  __restrict__ bias,
    const float*  __restrict__ gamma,
    const float*  __restrict__ beta,
    float* __restrict__ out)
{
    extern __shared__ char smem[];
    uint32_t sb = smem_u32(smem);
    const unsigned FULL = 0xFFFFFFFFu;
    int tid = threadIdx.x;
    int tx  = tid & 31;
    int wid = tid >> 5;
    int row0 = blockIdx.x * MT;

    int g = tx >> 2;          // fragment group (0..7)
    int t = tx & 3;           // thread-in-group
    int warpM = wid >> 2;     // 0..1
    int warpN = wid & 3;      // 0..3
    int mrow = warpM * 32;
    int n0   = warpN * 64;

    ((float*)(smem + SM_BIAS))[tid]  = bias[tid];
    ((float*)(smem + SM_GAMMA))[tid] = gamma[tid];
    ((float*)(smem + SM_BETA))[tid]  = beta[tid];

    // ---- int64-vs-int32 detection (offset valid under both interpretations)
    int okbit = 1;
    {
        const ull* pw = (const ull*)nbr;
        if (tx < 8) okbit = (pw[(size_t)row0 * (KNB / 2) + tx] < (ull)N_NODES);
    }
    int is64 = (__ballot_sync(FULL, okbit) == FULL);

    // ---------------- Phase 1: weighted gather (2 rows in flight) --------
    #pragma unroll 1
    for (int i = 0; i < 8; i += 2) {
        int lr0 = wid * 8 + i;
        int lr1 = lr0 + 1;
        int node0 = row0 + lr0, node1 = row0 + lr1;
        float wv0 = 0.f, wv1 = 0.f;
        int idx0 = 0, idx1 = 0;
        if (tx < KNB) {
            if (node0 < N_NODES) {
                wv0 = iw[(size_t)node0 * KNB + tx];
                if (is64) idx0 = (int)(((const long long*)nbr)[(size_t)node0 * KNB + tx]);
                else      idx0 = ((const int*)nbr)[(size_t)node0 * KNB + tx];
            }
            if (node1 < N_NODES) {
                wv1 = iw[(size_t)node1 * KNB + tx];
                if (is64) idx1 = (int)(((const long long*)nbr)[(size_t)node1 * KNB + tx]);
                else      idx1 = ((const int*)nbr)[(size_t)node1 * KNB + tx];
            }
        }
        float ws0 = wv0, ws1 = wv1;
        #pragma unroll
        for (int o = 1; o < 16; o <<= 1) {
            ws0 += __shfl_xor_sync(FULL, ws0, o);
            ws1 += __shfl_xor_sync(FULL, ws1, o);
        }
        ws0 = __shfl_sync(FULL, ws0, 0);
        ws1 = __shfl_sync(FULL, ws1, 0);
        float nw0 = (ws0 == 0.0f) ? (1.0f / (float)KNB) : (wv0 / ws0);
        float nw1 = (ws1 == 0.0f) ? (1.0f / (float)KNB) : (wv1 / ws1);

        float4 a00 = make_float4(0.f,0.f,0.f,0.f), a01 = a00;
        float4 a10 = a00, a11 = a00;
        #pragma unroll
        for (int k = 0; k < KNB; k++) {
            int   ik0 = __shfl_sync(FULL, idx0, k);
            float wk0 = __shfl_sync(FULL, nw0,  k);
            int   ik1 = __shfl_sync(FULL, idx1, k);
            float wk1 = __shfl_sync(FULL, nw1,  k);
            const float4* r0 = feats + (size_t)ik0 * (DIM / 4);
            const float4* r1 = feats + (size_t)ik1 * (DIM / 4);
            float4 f00 = r0[tx];
            float4 f01 = r0[tx + 32];
            float4 f10 = r1[tx];
            float4 f11 = r1[tx + 32];
            a00.x += wk0*f00.x; a00.y += wk0*f00.y; a00.z += wk0*f00.z; a00.w += wk0*f00.w;
            a01.x += wk0*f01.x; a01.y += wk0*f01.y; a01.z += wk0*f01.z; a01.w += wk0*f01.w;
            a10.x += wk1*f10.x; a10.y += wk1*f10.y; a10.z += wk1*f10.z; a10.w += wk1*f10.w;
            a11.x += wk1*f11.x; a11.y += wk1*f11.y; a11.z += wk1*f11.z; a11.w += wk1*f11.w;
        }
        store_split4(smem, lr0, tx, a00);
        store_split4(smem, lr0, tx + 32, a01);
        store_split4(smem, lr1, tx, a10);
        store_split4(smem, lr1, tx + 32, a11);
    }
    __syncthreads();   // A tiles complete; the ONLY mainloop barrier

    // ---------------- Phase 2: 3-term bf16 split GEMM (barrier-free) -----
    float d[2][8][4];
    #pragma unroll
    for (int mi = 0; mi < 2; mi++)
        #pragma unroll
        for (int ni = 0; ni < 8; ni++)
            #pragma unroll
            for (int j = 0; j < 4; j++) d[mi][ni][j] = 0.0f;

    // A ldmatrix lane addresses
    uint32_t a_lane = (uint32_t)((((tx >> 3) & 1) * 8 + (tx & 7)) * A_STRIDE_B
                                 + (tx >> 4) * 16);
    uint32_t a_hi = sb + SM_AHI + a_lane + (uint32_t)mrow * A_STRIDE_B;
    uint32_t a_lo = sb + SM_ALO + a_lane + (uint32_t)mrow * A_STRIDE_B;

    // B fragment pointers: this warp's 8 n8-tiles start at nt0 = n0/8
    const uint2* wh = g_wf_hi + ((size_t)(n0 >> 3) * NUM_KC) * 32 + tx;
    const uint2* wl = g_wf_lo + ((size_t)(n0 >> 3) * NUM_KC) * 32 + tx;

    #pragma unroll 1
    for (int kc = 0; kc < NUM_KC; kc++) {
        // B fragments for all 8 n8-tiles this chunk (batched LDG.64, L2-hit)
        uint2 BH[4], BL[4];
        size_t cb = (size_t)kc * 32;
        #pragma unroll
        for (int p = 0; p < 4; p++) {
            BH[p] = wh[(size_t)p * (NUM_KC * 32) + cb];
            BL[p] = wl[(size_t)p * (NUM_KC * 32) + cb];
        }
        // A fragments (hi+lo) for this k16
        uint32_t ah[2][4], al[2][4];
        uint32_t kb = (uint32_t)kc * 32;
        #pragma unroll
        for (int mi = 0; mi < 2; mi++) {
            ldmx4(ah[mi], a_hi + (uint32_t)mi * 16 * A_STRIDE_B + kb);
            ldmx4(al[mi], a_lo + (uint32_t)mi * 16 * A_STRIDE_B + kb);
        }
        #pragma unroll
        for (int p = 0; p < 4; p++) {
            #pragma unroll
            for (int mi = 0; mi < 2; mi++) {
                mma_bf16(d[mi][p], ah[mi], (const uint32_t*)&BH[p]);
                mma_bf16(d[mi][p], al[mi], (const uint32_t*)&BH[p]);
                mma_bf16(d[mi][p], ah[mi], (const uint32_t*)&BL[p]);
            }
        }
        // second half: n8-tiles 4..7
        #pragma unroll
        for (int p = 0; p < 4; p++) {
            BH[p] = wh[(size_t)(p + 4) * (NUM_KC * 32) + cb];
            BL[p] = wl[(size_t)(p + 4) * (NUM_KC * 32) + cb];
        }
        #pragma unroll
        for (int p = 0; p < 4; p++) {
            #pragma unroll
            for (int mi = 0; mi < 2; mi++) {
                mma_bf16(d[mi][p + 4], ah[mi], (const uint32_t*)&BH[p]);
                mma_bf16(d[mi][p + 4], al[mi], (const uint32_t*)&BH[p]);
                mma_bf16(d[mi][p + 4], ah[mi], (const uint32_t*)&BL[p]);
            }
        }
    }

    // ---------------- Phase 3: bias + LayerNorm + store ------------------
    const float* bias_s  = (const float*)(smem + SM_BIAS);
    const float* gamma_s = (const float*)(smem + SM_GAMMA);
    const float* beta_s  = (const float*)(smem + SM_BETA);
    float* ps = (float*)(smem + SM_PS);
    float* pq = (float*)(smem + SM_PQ);

    float v[2][8][4];
    float s[2][2], q[2][2];   // [mi][half]
    #pragma unroll
    for (int mi = 0; mi < 2; mi++) { s[mi][0]=s[mi][1]=q[mi][0]=q[mi][1]=0.f; }
    #pragma unroll
    for (int mi = 0; mi < 2; mi++)
        #pragma unroll
        for (int ni = 0; ni < 8; ni++) {
            int c0 = n0 + ni * 8 + 2 * t;
            float b0 = bias_s[c0], b1 = bias_s[c0 + 1];
            float x;
            x = d[mi][ni][0] + b0; v[mi][ni][0] = x; s[mi][0] += x; q[mi][0] += x * x;
            x = d[mi][ni][1] + b1; v[mi][ni][1] = x; s[mi][0] += x; q[mi][0] += x * x;
            x = d[mi][ni][2] + b0; v[mi][ni][2] = x; s[mi][1] += x; q[mi][1] += x * x;
            x = d[mi][ni][3] + b1; v[mi][ni][3] = x; s[mi][1] += x; q[mi][1] += x * x;
        }
    #pragma unroll
    for (int mi = 0; mi < 2; mi++)
        #pragma unroll
        for (int h = 0; h < 2; h++) {
            s[mi][h] += __shfl_xor_sync(FULL, s[mi][h], 1);
            s[mi][h] += __shfl_xor_sync(FULL, s[mi][h], 2);
            q[mi][h] += __shfl_xor_sync(FULL, q[mi][h], 1);
            q[mi][h] += __shfl_xor_sync(FULL, q[mi][h], 2);
        }
    if (t == 0) {
        #pragma unroll
        for (int mi = 0; mi < 2; mi++)
            #pragma unroll
            for (int h = 0; h < 2; h++) {
                int r = mrow + mi * 16 + g + 8 * h;
                ps[r * 4 + warpN] = s[mi][h];
                pq[r * 4 + warpN] = q[mi][h];
            }
    }
    __syncthreads();

    #pragma unroll
    for (int mi = 0; mi < 2; mi++)
        #pragma unroll
        for (int h = 0; h < 2; h++) {
            int r = mrow + mi * 16 + g + 8 * h;
            float st = ps[r*4+0] + ps[r*4+1] + ps[r*4+2] + ps[r*4+3];
            float qt = pq[r*4+0] + pq[r*4+1] + pq[r*4+2] + pq[r*4+3];
            float mean = st * (1.0f / DIM);
            float var  = qt * (1.0f / DIM) - mean * mean;
            float inv  = rsqrtf(var + LN_EPS);
            int node = row0 + r;
            if (node < N_NODES) {
                float* orow = out + (size_t)node * DIM;
                #pragma unroll
                for (int ni = 0; ni < 8; ni++) {
                    int c0 = n0 + ni * 8 + 2 * t;
                    float2 o;
                    float vv0 = v[mi][ni][h ? 2 : 0];
                    float vv1 = v[mi][ni][h ? 3 : 1];
                    o.x = (vv0 - mean) * inv * gamma_s[c0]     + beta_s[c0];
                    o.y = (vv1 - mean) * inv * gamma_s[c0 + 1] + beta_s[c0 + 1];
                    *(float2*)(orow + c0) = o;
                }
            }
        }
}

// ---------------------------------------------------------------------------
extern "C" void kernel_launch(void* const* d_in, const int* in_sizes, int n_in,
                              void* d_out, int out_size) {
    const float* features  = (const float*)d_in[0];
    const void*  neighbors = d_in[1];
    const float* iw        = (const float*)d_in[2];
    const float* W         = (const float*)d_in[3];
    const float* b         = (const float*)d_in[4];
    const float* gamma     = (const float*)d_in[5];
    const float* beta      = (const float*)d_in[6];
    float* out = (float*)d_out;

    cudaFuncSetAttribute(fused_mma_kernel,
                         cudaFuncAttributeMaxDynamicSharedMemorySize, SM_TOTAL);

    convert_w_kernel<<<64, 256>>>(W);   // 16384 threads

    int blocks = (N_NODES + MT - 1) / MT;   // 782
    fused_mma_kernel<<<blocks, THREADS, SM_TOTAL>>>(
        (const float4*)features, neighbors, iw, b, gamma, beta, out);
}